// round 1
// baseline (speedup 1.0000x reference)
#include <cuda_runtime.h>

// Problem constants
#define BQ     64
#define NQ     128
#define KQ     12
#define D_ATOM 256
#define D_NBR  320
#define D_NEW  256
#define HQ     8
#define DKQ    32
#define LN_EPS 1e-5f

// One CTA per (b,n): fused  h-GEMM + e-GEMM + GATv2 attention + LayerNorm.
// 256 threads:  tx = t>>2 owns 4 output columns (float4 of W row),
//               ty = t&3  splits the reduction dim 4 ways (shuffle-combined).
__global__ void __launch_bounds__(256, 2)
gnn_fused_kernel(const float* __restrict__ atom,     // (B*N, 256)
                 const float* __restrict__ nbr,      // (B*N, 12, 320)
                 const float* __restrict__ smask,    // (B*N, 12)  additive -1e9 on pad
                 const float* __restrict__ amask,    // (B*N, 12)  1 = valid
                 const float* __restrict__ Wa,       // (256, 256)
                 const float* __restrict__ ba,       // (256,)
                 const float* __restrict__ Wn,       // (320, 256)
                 const float* __restrict__ bnb,      // (256,)
                 const float* __restrict__ wal,      // (32,)
                 const float* __restrict__ bal,      // (1,)
                 const float* __restrict__ gamma,    // (256,)
                 const float* __restrict__ beta,     // (256,)
                 float* __restrict__ out)            // (B*N, 256)
{
    __shared__ float s_nbr[KQ][D_NBR];     // 15360 B
    __shared__ float s_e[KQ][D_NEW];       // 12288 B
    __shared__ float s_atom[D_ATOM];
    __shared__ float s_h[D_NEW];
    __shared__ float s_score[KQ][HQ];
    __shared__ float s_attn[KQ][HQ];
    __shared__ float s_smask[KQ];
    __shared__ float s_amask[KQ];
    __shared__ float s_wal[DKQ];
    __shared__ float s_red[8];
    __shared__ float s_red2[8];
    __shared__ float s_stat[2];

    const int bn_idx = blockIdx.x;          // 0 .. B*N-1
    const int t  = threadIdx.x;
    const int tx = t >> 2;                  // 0..63 : column group (4 cols)
    const int ty = t & 3;                   // 0..3  : reduction partition

    // ---------------- stage inputs into smem ----------------
    {
        const float4* np4 = (const float4*)(nbr + (size_t)bn_idx * (KQ * D_NBR));
        float4* sn4 = (float4*)&s_nbr[0][0];
        for (int i = t; i < (KQ * D_NBR) / 4; i += 256) sn4[i] = np4[i];
        s_atom[t] = atom[(size_t)bn_idx * D_ATOM + t];
        if (t < KQ) {
            s_smask[t] = smask[bn_idx * KQ + t];
            s_amask[t] = amask[bn_idx * KQ + t];
        }
        if (t < DKQ) s_wal[t] = wal[t];
    }
    __syncthreads();

    // ---------------- h = atom @ Wa  (256 x 256) ----------------
    float h0 = 0.f, h1 = 0.f, h2 = 0.f, h3 = 0.f;
    {
        const int c0 = ty * (D_ATOM / 4);
        #pragma unroll 4
        for (int c = c0; c < c0 + D_ATOM / 4; ++c) {
            float4 w = *(const float4*)&Wa[c * D_NEW + tx * 4];
            float a = s_atom[c];
            h0 = fmaf(a, w.x, h0);
            h1 = fmaf(a, w.y, h1);
            h2 = fmaf(a, w.z, h2);
            h3 = fmaf(a, w.w, h3);
        }
    }

    // ---------------- e = nbr @ Wn  (12 x 320 x 256) ----------------
    float acc[KQ][4];
    #pragma unroll
    for (int k = 0; k < KQ; ++k) {
        acc[k][0] = 0.f; acc[k][1] = 0.f; acc[k][2] = 0.f; acc[k][3] = 0.f;
    }
    {
        const int c0 = ty * (D_NBR / 4);
        #pragma unroll 2
        for (int c = c0; c < c0 + D_NBR / 4; ++c) {
            float4 w = *(const float4*)&Wn[c * D_NEW + tx * 4];
            #pragma unroll
            for (int k = 0; k < KQ; ++k) {
                float f = s_nbr[k][c];
                acc[k][0] = fmaf(f, w.x, acc[k][0]);
                acc[k][1] = fmaf(f, w.y, acc[k][1]);
                acc[k][2] = fmaf(f, w.z, acc[k][2]);
                acc[k][3] = fmaf(f, w.w, acc[k][3]);
            }
        }
    }

    // combine the 4 reduction partitions: ty lives in lane bits [0:2)
    #pragma unroll
    for (int k = 0; k < KQ; ++k) {
        #pragma unroll
        for (int j = 0; j < 4; ++j) {
            float v = acc[k][j];
            v += __shfl_xor_sync(0xffffffffu, v, 1);
            v += __shfl_xor_sync(0xffffffffu, v, 2);
            acc[k][j] = v;
        }
    }
    h0 += __shfl_xor_sync(0xffffffffu, h0, 1); h0 += __shfl_xor_sync(0xffffffffu, h0, 2);
    h1 += __shfl_xor_sync(0xffffffffu, h1, 1); h1 += __shfl_xor_sync(0xffffffffu, h1, 2);
    h2 += __shfl_xor_sync(0xffffffffu, h2, 1); h2 += __shfl_xor_sync(0xffffffffu, h2, 2);
    h3 += __shfl_xor_sync(0xffffffffu, h3, 1); h3 += __shfl_xor_sync(0xffffffffu, h3, 2);

    if (ty == 0) {
        float4 bv = *(const float4*)&bnb[tx * 4];
        #pragma unroll
        for (int k = 0; k < KQ; ++k) {
            s_e[k][tx * 4 + 0] = acc[k][0] + bv.x;
            s_e[k][tx * 4 + 1] = acc[k][1] + bv.y;
            s_e[k][tx * 4 + 2] = acc[k][2] + bv.z;
            s_e[k][tx * 4 + 3] = acc[k][3] + bv.w;
        }
        float4 bav = *(const float4*)&ba[tx * 4];
        s_h[tx * 4 + 0] = h0 + bav.x;
        s_h[tx * 4 + 1] = h1 + bav.y;
        s_h[tx * 4 + 2] = h2 + bav.z;
        s_h[tx * 4 + 3] = h3 + bav.w;
    }
    __syncthreads();

    // ---------------- GATv2 scores: leaky_relu(h + e) . w_align ----------------
    if (t < KQ * HQ) {                       // 96 threads: k = t/8, head = t%8
        const int k = t >> 3;
        const int hh = t & 7;
        const int base = hh * DKQ;
        float sc = 0.f;
        #pragma unroll 8
        for (int i = 0; i < DKQ; ++i) {
            float x = s_h[base + i] + s_e[k][base + i];
            x = fmaxf(x, 0.01f * x);          // leaky_relu, slope 0.01
            sc = fmaf(x, s_wal[i], sc);
        }
        s_score[k][hh] = sc + bal[0] + s_smask[k];
    }
    __syncthreads();

    // ---------------- softmax over K per head ----------------
    if (t < HQ) {
        const int hh = t;
        float mx = -3.4e38f;
        #pragma unroll
        for (int k = 0; k < KQ; ++k) mx = fmaxf(mx, s_score[k][hh]);
        float sum = 0.f;
        float ex[KQ];
        #pragma unroll
        for (int k = 0; k < KQ; ++k) { ex[k] = __expf(s_score[k][hh] - mx); sum += ex[k]; }
        float inv = 1.f / sum;
        #pragma unroll
        for (int k = 0; k < KQ; ++k) s_attn[k][hh] = ex[k] * inv * s_amask[k];
    }
    __syncthreads();

    // ---------------- ctx = sum_k attn * e ; LayerNorm ----------------
    const int hh = t >> 5;                    // head of this output column
    float ctx = 0.f;
    #pragma unroll
    for (int k = 0; k < KQ; ++k) ctx = fmaf(s_attn[k][hh], s_e[k][t], ctx);

    // block reduction of sum / sumsq over the 256 channels
    float v = ctx, v2 = ctx * ctx;
    #pragma unroll
    for (int o = 16; o > 0; o >>= 1) {
        v  += __shfl_xor_sync(0xffffffffu, v, o);
        v2 += __shfl_xor_sync(0xffffffffu, v2, o);
    }
    const int warp = t >> 5, lane = t & 31;
    if (lane == 0) { s_red[warp] = v; s_red2[warp] = v2; }
    __syncthreads();
    if (t == 0) {
        float s = 0.f, s2 = 0.f;
        #pragma unroll
        for (int w = 0; w < 8; ++w) { s += s_red[w]; s2 += s_red2[w]; }
        float mu = s * (1.f / D_NEW);
        float var = s2 * (1.f / D_NEW) - mu * mu;
        s_stat[0] = mu;
        s_stat[1] = rsqrtf(var + LN_EPS);
    }
    __syncthreads();
    const float mu = s_stat[0];
    const float inv = s_stat[1];
    out[(size_t)bn_idx * D_NEW + t] = (ctx - mu) * inv * gamma[t] + beta[t];
}

extern "C" void kernel_launch(void* const* d_in, const int* in_sizes, int n_in,
                              void* d_out, int out_size)
{
    (void)in_sizes; (void)n_in; (void)out_size;
    const float* atom   = (const float*)d_in[0];
    const float* nbr    = (const float*)d_in[1];
    const float* smask  = (const float*)d_in[2];
    const float* amask  = (const float*)d_in[3];
    const float* Wa     = (const float*)d_in[4];
    const float* ba     = (const float*)d_in[5];
    const float* Wn     = (const float*)d_in[6];
    const float* bnb    = (const float*)d_in[7];
    const float* wal    = (const float*)d_in[8];
    const float* bal    = (const float*)d_in[9];
    const float* gamma  = (const float*)d_in[10];
    const float* beta   = (const float*)d_in[11];
    float* out = (float*)d_out;

    gnn_fused_kernel<<<BQ * NQ, 256>>>(atom, nbr, smask, amask,
                                       Wa, ba, Wn, bnb, wal, bal,
                                       gamma, beta, out);
}

// round 2
// speedup vs baseline: 2.6392x; 2.6392x over previous
#include <cuda_runtime.h>

#define KQ     12
#define D_NBR  320
#define D_NEW  256
#define HQ     8
#define DKQ    32
#define A_CTA  2          // atoms per CTA
#define THREADS 128
#define LN_EPS 1e-5f

typedef unsigned long long u64;

__device__ __forceinline__ u64 pack2(float f) {
    u64 d; asm("mov.b64 %0, {%1, %1};" : "=l"(d) : "f"(f)); return d;
}
__device__ __forceinline__ u64 ffma2(u64 a, u64 b, u64 c) {
    u64 d; asm("fma.rn.f32x2 %0, %1, %2, %3;" : "=l"(d) : "l"(a), "l"(b), "l"(c)); return d;
}
__device__ __forceinline__ u64 fadd2(u64 a, u64 b) {
    u64 d; asm("add.rn.f32x2 %0, %1, %2;" : "=l"(d) : "l"(a), "l"(b)); return d;
}

// One CTA = 2 atoms. 128 threads: g = t>>6 selects atom, tx = t&63 owns cols [4tx, 4tx+4).
// e-GEMM: each W LDG.128 (as packed f32x2 pairs) feeds 12 neighbor rows via FFMA2.
__global__ void __launch_bounds__(THREADS, 4)
gnn_fused2(const float* __restrict__ atom,    // (B*N, 256)
           const float* __restrict__ nbr,     // (B*N, 12, 320)
           const float* __restrict__ smask,   // (B*N, 12)
           const float* __restrict__ amask,   // (B*N, 12)
           const float* __restrict__ Wa,      // (256, 256)
           const float* __restrict__ ba,      // (256,)
           const float* __restrict__ Wn,      // (320, 256)
           const float* __restrict__ bnb,     // (256,)
           const float* __restrict__ wal,     // (32,)
           const float* __restrict__ bal,     // (1,)
           const float* __restrict__ gamma,   // (256,)
           const float* __restrict__ beta,    // (256,)
           float* __restrict__ out)           // (B*N, 256)
{
    __shared__ float s_buf[A_CTA * KQ * D_NBR];   // nbr, later overlaid by e (A_CTA*12*256)
    __shared__ float s_atom[A_CTA * 256];
    __shared__ float s_h[A_CTA * 256];
    __shared__ float s_score[A_CTA][KQ][HQ];
    __shared__ float s_attn[A_CTA][KQ][HQ];
    __shared__ float s_smask[A_CTA * KQ];
    __shared__ float s_amask[A_CTA * KQ];
    __shared__ float s_wal[DKQ];
    __shared__ float s_bal;
    __shared__ float s_red[4][2];
    __shared__ float s_stat[A_CTA][2];

    const int t   = threadIdx.x;
    const int g   = t >> 6;                  // atom within CTA
    const int tx  = t & 63;                  // column group
    const int bn0 = blockIdx.x * A_CTA;

    // ---------------- stage ----------------
    {
        const float4* src = (const float4*)(nbr + (size_t)bn0 * (KQ * D_NBR));
        float4* dst = (float4*)s_buf;
        #pragma unroll
        for (int i = 0; i < (A_CTA * KQ * D_NBR) / 4 / THREADS; ++i)   // 15
            dst[t + i * THREADS] = src[t + i * THREADS];
        ((float4*)s_atom)[t] = ((const float4*)(atom + (size_t)bn0 * 256))[t];
        if (t < A_CTA * KQ) {
            s_smask[t] = smask[bn0 * KQ + t];
            s_amask[t] = amask[bn0 * KQ + t];
        }
        if (t < DKQ) s_wal[t] = wal[t];
        if (t == 64) s_bal = bal[0];
    }
    __syncthreads();

    // ---------------- e-GEMM: 12 rows x 4 cols per thread, packed f32x2 ----------------
    u64 acc[KQ][2];
    #pragma unroll
    for (int r = 0; r < KQ; ++r) { acc[r][0] = 0ull; acc[r][1] = 0ull; }

    const float* nb = s_buf + g * (KQ * D_NBR);
    #pragma unroll 1
    for (int c0 = 0; c0 < D_NBR; c0 += 4) {
        u64 wlo[4], whi[4];
        #pragma unroll
        for (int i = 0; i < 4; ++i) {
            ulonglong2 wv = *(const ulonglong2*)(Wn + (size_t)(c0 + i) * D_NEW + tx * 4);
            wlo[i] = wv.x; whi[i] = wv.y;
        }
        #pragma unroll
        for (int r = 0; r < KQ; ++r) {
            float4 f = *(const float4*)(nb + r * D_NBR + c0);   // warp-uniform broadcast
            u64 p;
            p = pack2(f.x); acc[r][0] = ffma2(p, wlo[0], acc[r][0]); acc[r][1] = ffma2(p, whi[0], acc[r][1]);
            p = pack2(f.y); acc[r][0] = ffma2(p, wlo[1], acc[r][0]); acc[r][1] = ffma2(p, whi[1], acc[r][1]);
            p = pack2(f.z); acc[r][0] = ffma2(p, wlo[2], acc[r][0]); acc[r][1] = ffma2(p, whi[2], acc[r][1]);
            p = pack2(f.w); acc[r][0] = ffma2(p, wlo[3], acc[r][0]); acc[r][1] = ffma2(p, whi[3], acc[r][1]);
        }
    }

    // ---------------- h-GEMM ----------------
    u64 h0 = 0ull, h1 = 0ull;
    #pragma unroll 1
    for (int c0 = 0; c0 < 256; c0 += 4) {
        u64 wlo[4], whi[4];
        #pragma unroll
        for (int i = 0; i < 4; ++i) {
            ulonglong2 wv = *(const ulonglong2*)(Wa + (size_t)(c0 + i) * D_NEW + tx * 4);
            wlo[i] = wv.x; whi[i] = wv.y;
        }
        float4 a4 = *(const float4*)(s_atom + g * 256 + c0);
        u64 p;
        p = pack2(a4.x); h0 = ffma2(p, wlo[0], h0); h1 = ffma2(p, whi[0], h1);
        p = pack2(a4.y); h0 = ffma2(p, wlo[1], h0); h1 = ffma2(p, whi[1], h1);
        p = pack2(a4.z); h0 = ffma2(p, wlo[2], h0); h1 = ffma2(p, whi[2], h1);
        p = pack2(a4.w); h0 = ffma2(p, wlo[3], h0); h1 = ffma2(p, whi[3], h1);
    }

    __syncthreads();   // all nbr reads done before e overlays s_buf

    // ---------------- write e (+bias) and h (+bias) ----------------
    {
        ulonglong2 bv = *(const ulonglong2*)(bnb + tx * 4);
        #pragma unroll
        for (int r = 0; r < KQ; ++r) {
            u64* p = (u64*)(s_buf + (g * KQ + r) * D_NEW + tx * 4);
            p[0] = fadd2(acc[r][0], bv.x);
            p[1] = fadd2(acc[r][1], bv.y);
        }
        ulonglong2 bav = *(const ulonglong2*)(ba + tx * 4);
        u64* ph = (u64*)(s_h + g * 256 + tx * 4);
        ph[0] = fadd2(h0, bav.x);
        ph[1] = fadd2(h1, bav.y);
    }
    __syncthreads();

    // ---------------- GATv2 scores ----------------
    const float bal0 = s_bal;
    for (int idx = t; idx < A_CTA * KQ * HQ; idx += THREADS) {   // 192 tasks
        const int gg  = idx / (KQ * HQ);
        const int rem = idx - gg * (KQ * HQ);
        const int k   = rem >> 3;
        const int hh  = rem & 7;
        const float* hv = s_h  + gg * 256 + hh * DKQ;
        const float* ev = s_buf + (gg * KQ + k) * D_NEW + hh * DKQ;
        float sc = 0.f;
        #pragma unroll
        for (int i = 0; i < DKQ; ++i) {
            float x = hv[i] + ev[i];
            x = fmaxf(x, 0.01f * x);
            sc = fmaf(x, s_wal[i], sc);
        }
        s_score[gg][k][hh] = sc + bal0 + s_smask[gg * KQ + k];
    }
    __syncthreads();

    // ---------------- softmax over K per (atom, head) ----------------
    if (t < A_CTA * HQ) {                    // 16 tasks
        const int gg = t >> 3, hh = t & 7;
        float mx = -3.4e38f;
        #pragma unroll
        for (int k = 0; k < KQ; ++k) mx = fmaxf(mx, s_score[gg][k][hh]);
        float ex[KQ], sum = 0.f;
        #pragma unroll
        for (int k = 0; k < KQ; ++k) { ex[k] = __expf(s_score[gg][k][hh] - mx); sum += ex[k]; }
        const float inv = 1.f / sum;
        #pragma unroll
        for (int k = 0; k < KQ; ++k) s_attn[gg][k][hh] = ex[k] * inv * s_amask[gg * KQ + k];
    }
    __syncthreads();

    // ---------------- ctx + LayerNorm ----------------
    const int hh = tx >> 3;                  // head of this 4-col group
    float c0 = 0.f, c1 = 0.f, c2 = 0.f, c3 = 0.f;
    #pragma unroll
    for (int k = 0; k < KQ; ++k) {
        const float a = s_attn[g][k][hh];
        const float4 ev = *(const float4*)(s_buf + (g * KQ + k) * D_NEW + tx * 4);
        c0 = fmaf(a, ev.x, c0);
        c1 = fmaf(a, ev.y, c1);
        c2 = fmaf(a, ev.z, c2);
        c3 = fmaf(a, ev.w, c3);
    }
    float v  = c0 + c1 + c2 + c3;
    float v2 = c0 * c0 + c1 * c1 + c2 * c2 + c3 * c3;
    #pragma unroll
    for (int o = 16; o > 0; o >>= 1) {
        v  += __shfl_xor_sync(0xffffffffu, v, o);
        v2 += __shfl_xor_sync(0xffffffffu, v2, o);
    }
    const int warp = t >> 5, lane = t & 31;
    if (lane == 0) { s_red[warp][0] = v; s_red[warp][1] = v2; }
    __syncthreads();
    if (t < A_CTA) {
        const float s  = s_red[2 * t][0] + s_red[2 * t + 1][0];
        const float s2 = s_red[2 * t][1] + s_red[2 * t + 1][1];
        const float mu  = s * (1.f / D_NEW);
        const float var = s2 * (1.f / D_NEW) - mu * mu;
        s_stat[t][0] = mu;
        s_stat[t][1] = rsqrtf(var + LN_EPS);
    }
    __syncthreads();
    const float mu  = s_stat[g][0];
    const float inv = s_stat[g][1];
    const float4 gv = *(const float4*)(gamma + tx * 4);
    const float4 bv = *(const float4*)(beta + tx * 4);
    float4 o;
    o.x = (c0 - mu) * inv * gv.x + bv.x;
    o.y = (c1 - mu) * inv * gv.y + bv.y;
    o.z = (c2 - mu) * inv * gv.z + bv.z;
    o.w = (c3 - mu) * inv * gv.w + bv.w;
    *(float4*)(out + (size_t)(bn0 + g) * D_NEW + tx * 4) = o;
}

extern "C" void kernel_launch(void* const* d_in, const int* in_sizes, int n_in,
                              void* d_out, int out_size)
{
    (void)in_sizes; (void)n_in; (void)out_size;
    const float* atom   = (const float*)d_in[0];
    const float* nbr    = (const float*)d_in[1];
    const float* smask  = (const float*)d_in[2];
    const float* amask  = (const float*)d_in[3];
    const float* Wa     = (const float*)d_in[4];
    const float* ba     = (const float*)d_in[5];
    const float* Wn     = (const float*)d_in[6];
    const float* bnb    = (const float*)d_in[7];
    const float* wal    = (const float*)d_in[8];
    const float* bal    = (const float*)d_in[9];
    const float* gamma  = (const float*)d_in[10];
    const float* beta   = (const float*)d_in[11];
    float* out = (float*)d_out;

    gnn_fused2<<<(64 * 128) / A_CTA, THREADS>>>(atom, nbr, smask, amask,
                                                Wa, ba, Wn, bnb, wal, bal,
                                                gamma, beta, out);
}